// round 10
// baseline (speedup 1.0000x reference)
#include <cuda_runtime.h>

#define H  64
#define LL 2048
#define VOCAB 64
#define NBLK 32
#define FULL 0xffffffffu

// -------- device-global scratch (no runtime allocation allowed) --------
__device__ __align__(16) float g_ktab[VOCAB * H];    // normalized k per vocab id
__device__ __align__(16) float g_vtab[VOCAB * H];    // v per vocab id
__device__ __align__(16) float g_qtab[VOCAB * H];    // q per vocab id
__device__ __align__(16) float g_KKn[VOCAB * VOCAB]; // NEGATED Gram of k table
__device__ __align__(16) float g_Wcomb[H * H];       // Wout @ Wrp
__device__ __align__(16) float g_bcomb[H];           // Wout @ brp + bout
__device__ unsigned g_bar1 = 0, g_bar2 = 0, g_rst = 0;   // spin barriers

__device__ __forceinline__ float bfly_sum(float v) {
    #pragma unroll
    for (int o = 16; o; o >>= 1) v += __shfl_xor_sync(FULL, v, o);
    return v;
}

// ======================================================================
// Single fused kernel. grid 32, block 256 (8 warps).
//   Phase A: two 128-thread halves encode vocab 2b, 2b+1.  -> barrier 1
//   Phase B: negated KK rows; 8 warps compute R-init for their batches.
//   Phase C: 4 scan warps (1/SMSP), each SIMD-folding TWO batches:
//            batch A on lanes 0-15, batch B on lanes 16-31 (R 4/lane).
//            One instruction stream drives both batches; warps 4-7 are
//            parked at the barrier (no issue-slot cost).
// ======================================================================
__global__ void __launch_bounds__(256) fused_kernel(
    const int*   __restrict__ seq,
    const float* __restrict__ embed, const float* __restrict__ W1,
    const float* __restrict__ b1, const float* __restrict__ W2,
    const float* __restrict__ b2, const float* __restrict__ gamma,
    const float* __restrict__ beta, const float* __restrict__ Wk,
    const float* __restrict__ Wv, const float* __restrict__ Wq,
    const float* __restrict__ Wrp, const float* __restrict__ brp,
    const float* __restrict__ Wout, const float* __restrict__ bout,
    float* __restrict__ out)
{
    __shared__ __align__(16) float sKKn[VOCAB * H];        // 16 KB
    __shared__ __align__(16) unsigned char sseq[8][LL];    // 16 KB
    __shared__ __align__(16) float e2[2][H], f12[2][2 * H];
    __shared__ __align__(16) float h2[2][H], hs2[2][H];
    __shared__ __align__(16) float sRi[8][H];              // R-init handoff
    __shared__ __align__(16) float sMq[8][H];              // Mq handoff
    __shared__ float s_mu[2], s_rstd[2], s_kinv[2];

    const int tid  = threadIdx.x;
    const int lane = tid & 31;
    const int w    = tid >> 5;            // warp 0..7
    const int half = tid >> 7;            // 0 or 1 (phase A/B halves)
    const int t128 = tid & 127;
    const int v0   = blockIdx.x * 2 + half;
    const int lo2  = 2 * lane;
    const int b    = blockIdx.x * 8 + w;  // batch this warp stages/inits

    float* e  = e2[half];
    float* f1 = f12[half];
    float* h  = h2[half];
    float* hs = hs2[half];

    // ---- stage this block's 8 sequences (warp w -> batch b) ----
    {
        const int4* sg = (const int4*)(seq + b * LL);
        uchar4* ssh = (uchar4*)sseq[w];
        #pragma unroll 4
        for (int i = lane; i < LL / 4; i += 32) {
            int4 t = sg[i];
            ssh[i] = make_uchar4((unsigned char)t.x, (unsigned char)t.y,
                                 (unsigned char)t.z, (unsigned char)t.w);
        }
    }

    // ================= Phase A: encode vocab v0 (per half) =================
    if (t128 < H) e[t128] = embed[v0 * H + t128];
    __syncthreads();

    {   // ff1 = relu(W1 e + b1)
        const float4* w4 = (const float4*)(W1 + t128 * H);
        const float4* e4 = (const float4*)e;
        float a0 = 0.f, a1 = 0.f, a2 = 0.f, a3 = 0.f;
        #pragma unroll
        for (int i = 0; i < 16; i++) {
            float4 ww = w4[i], ee = e4[i];
            a0 = fmaf(ww.x, ee.x, a0); a1 = fmaf(ww.y, ee.y, a1);
            a2 = fmaf(ww.z, ee.z, a2); a3 = fmaf(ww.w, ee.w, a3);
        }
        f1[t128] = fmaxf((a0 + a1) + (a2 + a3) + b1[t128], 0.0f);
    }
    __syncthreads();

    if (t128 < H) {   // h = e + W2 ff1 + b2
        const float4* w4 = (const float4*)(W2 + t128 * 2 * H);
        const float4* f4 = (const float4*)f1;
        float a0 = 0.f, a1 = 0.f, a2 = 0.f, a3 = 0.f;
        float b0 = 0.f, c1 = 0.f, c2 = 0.f, b3 = 0.f;
        #pragma unroll
        for (int i = 0; i < 32; i += 2) {
            float4 ww = w4[i], ff = f4[i];
            a0 = fmaf(ww.x, ff.x, a0); a1 = fmaf(ww.y, ff.y, a1);
            a2 = fmaf(ww.z, ff.z, a2); a3 = fmaf(ww.w, ff.w, a3);
            float4 w2_ = w4[i + 1], ff2 = f4[i + 1];
            b0 = fmaf(w2_.x, ff2.x, b0); c1 = fmaf(w2_.y, ff2.y, c1);
            c2 = fmaf(w2_.z, ff2.z, c2); b3 = fmaf(w2_.w, ff2.w, b3);
        }
        h[t128] = e[t128] + ((a0 + a1) + (a2 + a3)) + ((b0 + c1) + (c2 + b3)) + b2[t128];
    }
    __syncthreads();

    if (t128 < 32) {   // LayerNorm stats (biased var, eps 1e-5)
        float x = bfly_sum(h[t128] + h[t128 + 32]);
        float mu = x * (1.0f / H);
        float c0 = h[t128] - mu, c1_ = h[t128 + 32] - mu;
        float vv = bfly_sum(c0 * c0 + c1_ * c1_);
        if (t128 == 0) { s_mu[half] = mu; s_rstd[half] = rsqrtf(vv * (1.0f / H) + 1e-5f); }
    }
    __syncthreads();
    if (t128 < H) hs[t128] = (h[t128] - s_mu[half]) * s_rstd[half] * gamma[t128] + beta[t128];
    __syncthreads();

    if (t128 < H) {   // k (raw) and q projections
        const float4* wk4 = (const float4*)(Wk + t128 * H);
        const float4* wq4 = (const float4*)(Wq + t128 * H);
        const float4* h4 = (const float4*)hs;
        float k0 = 0.f, k1 = 0.f, k2 = 0.f, k3 = 0.f;
        float q0 = 0.f, q1 = 0.f, q2 = 0.f, q3 = 0.f;
        #pragma unroll
        for (int i = 0; i < 16; i++) {
            float4 wk = wk4[i], wq = wq4[i], hh = h4[i];
            k0 = fmaf(wk.x, hh.x, k0); k1 = fmaf(wk.y, hh.y, k1);
            k2 = fmaf(wk.z, hh.z, k2); k3 = fmaf(wk.w, hh.w, k3);
            q0 = fmaf(wq.x, hh.x, q0); q1 = fmaf(wq.y, hh.y, q1);
            q2 = fmaf(wq.z, hh.z, q2); q3 = fmaf(wq.w, hh.w, q3);
        }
        h[t128] = (k0 + k1) + (k2 + k3);
        g_qtab[v0 * H + t128] = (q0 + q1) + (q2 + q3);
    } else {         // v projection
        const int i = t128 - H;
        const float4* wv4 = (const float4*)(Wv + i * H);
        const float4* h4 = (const float4*)hs;
        float a0 = 0.f, a1 = 0.f, a2 = 0.f, a3 = 0.f;
        #pragma unroll
        for (int j = 0; j < 16; j++) {
            float4 ww = wv4[j], hh = h4[j];
            a0 = fmaf(ww.x, hh.x, a0); a1 = fmaf(ww.y, hh.y, a1);
            a2 = fmaf(ww.z, hh.z, a2); a3 = fmaf(ww.w, hh.w, a3);
        }
        g_vtab[v0 * H + i] = (a0 + a1) + (a2 + a3);
    }
    __syncthreads();

    if (t128 < 32) {   // k normalization
        float n = bfly_sum(h[t128] * h[t128] + h[t128 + 32] * h[t128 + 32]);
        if (t128 == 0) s_kinv[half] = 1.0f / fmaxf(sqrtf(n), 1e-12f);
    }
    __syncthreads();
    if (t128 < H) {
        float kv = h[t128] * s_kinv[half];
        g_ktab[v0 * H + t128] = kv;
        hs[t128] = kv;                 // own k row for KK phase
    }

    // Wcomb row v0 + bcomb[v0]
    if (t128 < H) {
        float ww = 0.f, w1_ = 0.f;
        #pragma unroll
        for (int l = 0; l < H; l += 2) {
            ww  = fmaf(Wout[v0 * H + l],     Wrp[l * H + t128],       ww);
            w1_ = fmaf(Wout[v0 * H + l + 1], Wrp[(l + 1) * H + t128], w1_);
        }
        g_Wcomb[v0 * H + t128] = ww + w1_;
    }
    if (t128 == 0) {
        float bb = bout[v0], bb1 = 0.f;
        #pragma unroll
        for (int l = 0; l < H; l += 2) {
            bb  = fmaf(Wout[v0 * H + l],     brp[l],     bb);
            bb1 = fmaf(Wout[v0 * H + l + 1], brp[l + 1], bb1);
        }
        g_bcomb[v0] = bb + bb1;
    }

    // ---- barrier 1: all tables visible ----
    __syncthreads();
    if (tid == 0) {
        __threadfence();
        atomicAdd(&g_bar1, 1u);
        while (atomicAdd(&g_bar1, 0u) < (unsigned)NBLK) { }
        __threadfence();
    }
    __syncthreads();

    // ================= Phase B: negated KK row v0 (per half) =================
    if (t128 < H) {
        const int j = t128;
        const float4* kj4 = (const float4*)(g_ktab + j * H);
        const float4* ki4 = (const float4*)hs;
        float a0 = 0.f, a1 = 0.f, a2 = 0.f, a3 = 0.f;
        #pragma unroll
        for (int l = 0; l < 16; l++) {
            float4 ka = ki4[l], kb = __ldg(kj4 + l);
            a0 = fmaf(ka.x, kb.x, a0); a1 = fmaf(ka.y, kb.y, a1);
            a2 = fmaf(ka.z, kb.z, a2); a3 = fmaf(ka.w, kb.w, a3);
        }
        g_KKn[v0 * H + j] = -((a0 + a1) + (a2 + a3));
    }
    __syncthreads();
    if (tid == 0) { __threadfence(); atomicAdd(&g_bar2, 1u); }

    // ---- R-init: warp w computes batch b, hands off via smem ----
    {
        const unsigned char* myseq = sseq[w];
        const int qid = myseq[LL - 1];
        const float4* q4 = (const float4*)(g_qtab + qid * H);
        const float4* ka = (const float4*)(g_ktab + lo2 * H);
        const float4* kb = (const float4*)(g_ktab + (lo2 + 1) * H);
        float x0 = 0.f, x1 = 0.f, y0 = 0.f, y1 = 0.f;
        #pragma unroll
        for (int i = 0; i < 16; i += 2) {
            float4 q0 = __ldg(q4 + i),     a0 = __ldg(ka + i),     b0 = __ldg(kb + i);
            float4 q1 = __ldg(q4 + i + 1), a1 = __ldg(ka + i + 1), b1 = __ldg(kb + i + 1);
            x0 = fmaf(a0.x, q0.x, x0); x0 = fmaf(a0.y, q0.y, x0);
            x0 = fmaf(a0.z, q0.z, x0); x0 = fmaf(a0.w, q0.w, x0);
            x1 = fmaf(a1.x, q1.x, x1); x1 = fmaf(a1.y, q1.y, x1);
            x1 = fmaf(a1.z, q1.z, x1); x1 = fmaf(a1.w, q1.w, x1);
            y0 = fmaf(b0.x, q0.x, y0); y0 = fmaf(b0.y, q0.y, y0);
            y0 = fmaf(b0.z, q0.z, y0); y0 = fmaf(b0.w, q0.w, y0);
            y1 = fmaf(b1.x, q1.x, y1); y1 = fmaf(b1.y, q1.y, y1);
            y1 = fmaf(b1.z, q1.z, y1); y1 = fmaf(b1.w, q1.w, y1);
        }
        sRi[w][lo2]     = x0 + x1;
        sRi[w][lo2 + 1] = y0 + y1;
    }

    // ---- barrier 2 wait: all KK rows visible ----
    if (tid == 0) {
        while (atomicAdd(&g_bar2, 0u) < (unsigned)NBLK) { }
        __threadfence();
    }
    __syncthreads();

    // ---- stage negated KK into smem ----
    {
        const float4* gg = (const float4*)g_KKn;
        float4* ks = (float4*)sKKn;
        #pragma unroll
        for (int i = tid; i < VOCAB * H / 4; i += 256) ks[i] = __ldg(gg + i);
    }
    __syncthreads();

    // ====== Phase C: 4 scan warps, each SIMD-folding 2 batches ======
    if (w < 4) {
        const int hf   = lane >> 4;            // which batch half
        const int p    = lane & 15;            // position within half
        const int col  = 4 * p;                // 4 owned indices [col, col+4)
        const int bl   = 2 * w + hf;           // block-local batch 0..7
        const int hib  = hf << 4;              // SHFL source base
        const unsigned char* myseq = sseq[bl];

        float4 Rv = *(const float4*)&sRi[bl][col];
        float R0 = Rv.x, R1 = Rv.y, R2 = Rv.z, R3 = Rv.w;
        float M0 = 0.f, M1 = 0.f, M2 = 0.f, M3 = 0.f;

        // 3 single steps: t = 2046, 2045, 2044
        #pragma unroll
        for (int t = LL - 2; t >= LL - 4; --t) {
            const int id = (int)myseq[t];
            const float tlo = (id & 1) ? R1 : R0;
            const float thi = (id & 1) ? R3 : R2;
            const float tt  = (id & 2) ? thi : tlo;
            const float s = __shfl_sync(FULL, tt, (id >> 2) + hib);
            const float4 kr = *(const float4*)&sKKn[(id << 6) + col];
            const float4 vr = __ldg((const float4*)&g_vtab[(id << 6) + col]);
            R0 = fmaf(kr.x, s, R0); R1 = fmaf(kr.y, s, R1);
            R2 = fmaf(kr.z, s, R2); R3 = fmaf(kr.w, s, R3);
            M0 = fmaf(vr.x, s, M0); M1 = fmaf(vr.y, s, M1);
            M2 = fmaf(vr.z, s, M2); M3 = fmaf(vr.w, s, M3);
        }

        // 511 groups of 4 with id prefetch
        unsigned u = *(const unsigned*)(myseq + (LL - 8));
        #pragma unroll 1
        for (int base = LL - 8; base >= 0; base -= 4) {
            const unsigned ids = u;
            const int nb = (base >= 4) ? base - 4 : 0;
            u = *(const unsigned*)(myseq + nb);

            const int id0 = (int)(ids >> 24);           // t = base+3 (largest)
            const int id1 = (int)((ids >> 16) & 0xffu);
            const int id2 = (int)((ids >> 8) & 0xffu);
            const int id3 = (int)(ids & 0xffu);

            const int r0 = id0 << 6, r1 = id1 << 6, r2 = id2 << 6, r3 = id3 << 6;

            // negated Gram entries (broadcast within half)
            const float g10 = sKKn[r1 + id0];
            const float g20 = sKKn[r2 + id0], g21 = sKKn[r2 + id1];
            const float g30 = sKKn[r3 + id0], g31 = sKKn[r3 + id1], g32 = sKKn[r3 + id2];

            // k rows (4 owned elems/lane) and v rows (via L2, off critical path)
            const float4 k0 = *(const float4*)&sKKn[r0 + col];
            const float4 k1 = *(const float4*)&sKKn[r1 + col];
            const float4 k2 = *(const float4*)&sKKn[r2 + col];
            const float4 k3 = *(const float4*)&sKKn[r3 + col];
            const float4 vv0 = __ldg((const float4*)&g_vtab[r0 + col]);
            const float4 vv1 = __ldg((const float4*)&g_vtab[r1 + col]);
            const float4 vv2 = __ldg((const float4*)&g_vtab[r2 + col]);
            const float4 vv3 = __ldg((const float4*)&g_vtab[r3 + col]);

            // gathers d_j = R[id_j]: 3 SELs + per-lane-source SHFL each
            const float a0lo = (id0 & 1) ? R1 : R0, a0hi = (id0 & 1) ? R3 : R2;
            const float a1lo = (id1 & 1) ? R1 : R0, a1hi = (id1 & 1) ? R3 : R2;
            const float a2lo = (id2 & 1) ? R1 : R0, a2hi = (id2 & 1) ? R3 : R2;
            const float a3lo = (id3 & 1) ? R1 : R0, a3hi = (id3 & 1) ? R3 : R2;
            const float t0 = (id0 & 2) ? a0hi : a0lo;
            const float t1 = (id1 & 2) ? a1hi : a1lo;
            const float t2 = (id2 & 2) ? a2hi : a2lo;
            const float t3 = (id3 & 2) ? a3hi : a3lo;
            const float d0 = __shfl_sync(FULL, t0, (id0 >> 2) + hib);
            const float d1 = __shfl_sync(FULL, t1, (id1 >> 2) + hib);
            const float d2 = __shfl_sync(FULL, t2, (id2 >> 2) + hib);
            const float d3 = __shfl_sync(FULL, t3, (id3 >> 2) + hib);

            // forward substitution (negated Gram -> pure FMA)
            const float s0 = d0;
            const float s1 = fmaf(g10, s0, d1);
            const float s2 = fmaf(g21, s1, fmaf(g20, s0, d2));
            const float s3 = fmaf(g32, s2, fmaf(g31, s1, fmaf(g30, s0, d3)));

            // R += (-KK row_j) * s_j (chained; 16 FMA)
            R0 = fmaf(k3.x, s3, fmaf(k2.x, s2, fmaf(k1.x, s1, fmaf(k0.x, s0, R0))));
            R1 = fmaf(k3.y, s3, fmaf(k2.y, s2, fmaf(k1.y, s1, fmaf(k0.y, s0, R1))));
            R2 = fmaf(k3.z, s3, fmaf(k2.z, s2, fmaf(k1.z, s1, fmaf(k0.z, s0, R2))));
            R3 = fmaf(k3.w, s3, fmaf(k2.w, s2, fmaf(k1.w, s1, fmaf(k0.w, s0, R3))));

            // Mq += vtab row_j * s_j (off critical path)
            M0 = fmaf(vv3.x, s3, fmaf(vv2.x, s2, fmaf(vv1.x, s1, fmaf(vv0.x, s0, M0))));
            M1 = fmaf(vv3.y, s3, fmaf(vv2.y, s2, fmaf(vv1.y, s1, fmaf(vv0.y, s0, M1))));
            M2 = fmaf(vv3.z, s3, fmaf(vv2.z, s2, fmaf(vv1.z, s1, fmaf(vv0.z, s0, M2))));
            M3 = fmaf(vv3.w, s3, fmaf(vv2.w, s2, fmaf(vv1.w, s1, fmaf(vv0.w, s0, M3))));
        }

        *(float4*)&sMq[bl][col] = make_float4(M0, M1, M2, M3);
    }
    __syncthreads();

    // ---- epilogue: warp w handles batch b ----
    #pragma unroll
    for (int rr = 0; rr < 2; rr++) {
        const int i = lane + 32 * rr;
        const float4* w4 = (const float4*)(g_Wcomb + i * H);
        const float4* m4 = (const float4*)sMq[w];
        float a0 = 0.f, a1 = 0.f, a2 = 0.f, a3 = 0.f;
        #pragma unroll
        for (int j = 0; j < 16; j++) {
            float4 ww = __ldg(w4 + j);
            float4 m = m4[j];
            a0 = fmaf(ww.x, m.x, a0); a1 = fmaf(ww.y, m.y, a1);
            a2 = fmaf(ww.z, m.z, a2); a3 = fmaf(ww.w, m.w, a3);
        }
        out[b * H + i] = (a0 + a1) + (a2 + a3) + g_bcomb[i];
    }

    // ---- reset spin barriers for the next (graph-replayed) launch ----
    __syncthreads();
    if (tid == 0) {
        __threadfence();
        if (atomicAdd(&g_rst, 1u) == (unsigned)(NBLK - 1)) {
            atomicExch(&g_bar1, 0u);
            atomicExch(&g_bar2, 0u);
            atomicExch(&g_rst, 0u);
        }
    }
}

// ======================================================================
extern "C" void kernel_launch(void* const* d_in, const int* in_sizes, int n_in,
                              void* d_out, int out_size)
{
    (void)in_sizes; (void)n_in; (void)out_size;
    const int*   seq   = (const int*)  d_in[0];
    const float* embed = (const float*)d_in[1];
    const float* W1    = (const float*)d_in[2];
    const float* b1    = (const float*)d_in[3];
    const float* W2    = (const float*)d_in[4];
    const float* b2    = (const float*)d_in[5];
    const float* gamma = (const float*)d_in[6];
    const float* beta  = (const float*)d_in[7];
    const float* Wk    = (const float*)d_in[8];
    const float* Wv    = (const float*)d_in[9];
    const float* Wq    = (const float*)d_in[10];
    const float* Wrp   = (const float*)d_in[11];
    const float* brp   = (const float*)d_in[12];
    const float* Wout  = (const float*)d_in[13];
    const float* bout  = (const float*)d_in[14];

    fused_kernel<<<NBLK, 256>>>(seq, embed, W1, b1, W2, b2, gamma, beta,
                                Wk, Wv, Wq, Wrp, brp, Wout, bout,
                                (float*)d_out);
}

// round 11
// speedup vs baseline: 1.3862x; 1.3862x over previous
#include <cuda_runtime.h>

#define H  64
#define LL 2048
#define VOCAB 64
#define NBLK 64
#define FULL 0xffffffffu

// -------- device-global scratch (no runtime allocation allowed) --------
__device__ __align__(16) float g_ktab[VOCAB * H];    // normalized k per vocab id
__device__ __align__(16) float g_vtab[VOCAB * H];    // v per vocab id
__device__ __align__(16) float g_qtab[VOCAB * H];    // q per vocab id
__device__ __align__(16) float g_KKn[VOCAB * VOCAB]; // NEGATED Gram of k table
__device__ __align__(16) float g_Wcomb[H * H];       // Wout @ Wrp
__device__ __align__(16) float g_bcomb[H];           // Wout @ brp + bout
__device__ unsigned g_bar1 = 0, g_bar2 = 0, g_rst = 0;   // spin barriers

__device__ __forceinline__ float bfly_sum(float v) {
    #pragma unroll
    for (int o = 16; o; o >>= 1) v += __shfl_xor_sync(FULL, v, o);
    return v;
}

// ---- packed f32x2 helpers (sm_103a FFMA2) ----
__device__ __forceinline__ unsigned long long pack2(float lo, float hi) {
    unsigned long long r;
    asm("mov.b64 %0, {%1, %2};" : "=l"(r)
        : "r"(__float_as_uint(lo)), "r"(__float_as_uint(hi)));
    return r;
}
__device__ __forceinline__ void unpack2(unsigned long long p, float& lo, float& hi) {
    unsigned ulo, uhi;
    asm("mov.b64 {%0, %1}, %2;" : "=r"(ulo), "=r"(uhi) : "l"(p));
    lo = __uint_as_float(ulo); hi = __uint_as_float(uhi);
}
__device__ __forceinline__ void fma2(unsigned long long& d,
                                     unsigned long long a, unsigned long long b) {
    asm("fma.rn.f32x2 %0, %1, %2, %0;" : "+l"(d) : "l"(a), "l"(b));
}

// ======================================================================
// Single fused kernel. grid 64, block 128 (1 warp/SMSP — proven R6 layout).
// Phase C: C=4 groups, packed FFMA2 R/Mq updates, software-pipelined
// loads in the SHFL shadow, direct packed Mq (no S-scatter).
// ======================================================================
__global__ void __launch_bounds__(128) fused_kernel(
    const int*   __restrict__ seq,
    const float* __restrict__ embed, const float* __restrict__ W1,
    const float* __restrict__ b1, const float* __restrict__ W2,
    const float* __restrict__ b2, const float* __restrict__ gamma,
    const float* __restrict__ beta, const float* __restrict__ Wk,
    const float* __restrict__ Wv, const float* __restrict__ Wq,
    const float* __restrict__ Wrp, const float* __restrict__ brp,
    const float* __restrict__ Wout, const float* __restrict__ bout,
    float* __restrict__ out)
{
    __shared__ __align__(16) float sTab[2 * VOCAB * H];   // [0:4096) -KK, [4096:8192) vtab
    __shared__ __align__(16) unsigned char sseq[4][LL];   // 8 KB
    __shared__ __align__(16) float e[H], f1[2 * H], h[H], hs[H];
    __shared__ __align__(16) float sRi[4][H];              // R-init handoff
    __shared__ __align__(16) float sMq[4][H];              // Mq handoff
    __shared__ float s_mu, s_rstd, s_kinv;

    const int v    = blockIdx.x;
    const int tid  = threadIdx.x;
    const int lane = tid & 31;
    const int w    = tid >> 5;
    const int lo2  = 2 * lane;
    const int b    = v * 4 + w;

    // ---- stage this block's 4 sequences (warp w stages batch b) ----
    {
        const int4* sg = (const int4*)(seq + b * LL);
        uchar4* ssh = (uchar4*)sseq[w];
        #pragma unroll 4
        for (int i = lane; i < LL / 4; i += 32) {
            int4 t = sg[i];
            ssh[i] = make_uchar4((unsigned char)t.x, (unsigned char)t.y,
                                 (unsigned char)t.z, (unsigned char)t.w);
        }
    }

    // ================= Phase A: encode vocab v =================
    if (tid < H) e[tid] = embed[v * H + tid];
    __syncthreads();

    {   // ff1 = relu(W1 e + b1)
        const float4* w4 = (const float4*)(W1 + tid * H);
        const float4* e4 = (const float4*)e;
        float a0 = 0.f, a1 = 0.f, a2 = 0.f, a3 = 0.f;
        #pragma unroll
        for (int i = 0; i < 16; i++) {
            float4 ww = w4[i], ee = e4[i];
            a0 = fmaf(ww.x, ee.x, a0); a1 = fmaf(ww.y, ee.y, a1);
            a2 = fmaf(ww.z, ee.z, a2); a3 = fmaf(ww.w, ee.w, a3);
        }
        f1[tid] = fmaxf((a0 + a1) + (a2 + a3) + b1[tid], 0.0f);
    }
    __syncthreads();

    if (tid < H) {   // h = e + W2 ff1 + b2
        const float4* w4 = (const float4*)(W2 + tid * 2 * H);
        const float4* f4 = (const float4*)f1;
        float a0 = 0.f, a1 = 0.f, a2 = 0.f, a3 = 0.f;
        float b0 = 0.f, c1 = 0.f, c2 = 0.f, b3 = 0.f;
        #pragma unroll
        for (int i = 0; i < 32; i += 2) {
            float4 ww = w4[i], ff = f4[i];
            a0 = fmaf(ww.x, ff.x, a0); a1 = fmaf(ww.y, ff.y, a1);
            a2 = fmaf(ww.z, ff.z, a2); a3 = fmaf(ww.w, ff.w, a3);
            float4 w2_ = w4[i + 1], ff2 = f4[i + 1];
            b0 = fmaf(w2_.x, ff2.x, b0); c1 = fmaf(w2_.y, ff2.y, c1);
            c2 = fmaf(w2_.z, ff2.z, c2); b3 = fmaf(w2_.w, ff2.w, b3);
        }
        h[tid] = e[tid] + ((a0 + a1) + (a2 + a3)) + ((b0 + c1) + (c2 + b3)) + b2[tid];
    }
    __syncthreads();

    if (tid < 32) {   // LayerNorm stats (biased var, eps 1e-5)
        float x = bfly_sum(h[tid] + h[tid + 32]);
        float mu = x * (1.0f / H);
        float c0 = h[tid] - mu, c1_ = h[tid + 32] - mu;
        float vv = bfly_sum(c0 * c0 + c1_ * c1_);
        if (tid == 0) { s_mu = mu; s_rstd = rsqrtf(vv * (1.0f / H) + 1e-5f); }
    }
    __syncthreads();
    if (tid < H) hs[tid] = (h[tid] - s_mu) * s_rstd * gamma[tid] + beta[tid];
    __syncthreads();

    if (tid < H) {   // k (raw) and q projections
        const float4* wk4 = (const float4*)(Wk + tid * H);
        const float4* wq4 = (const float4*)(Wq + tid * H);
        const float4* h4 = (const float4*)hs;
        float k0 = 0.f, k1 = 0.f, k2 = 0.f, k3 = 0.f;
        float q0 = 0.f, q1 = 0.f, q2 = 0.f, q3 = 0.f;
        #pragma unroll
        for (int i = 0; i < 16; i++) {
            float4 wk = wk4[i], wq = wq4[i], hh = h4[i];
            k0 = fmaf(wk.x, hh.x, k0); k1 = fmaf(wk.y, hh.y, k1);
            k2 = fmaf(wk.z, hh.z, k2); k3 = fmaf(wk.w, hh.w, k3);
            q0 = fmaf(wq.x, hh.x, q0); q1 = fmaf(wq.y, hh.y, q1);
            q2 = fmaf(wq.z, hh.z, q2); q3 = fmaf(wq.w, hh.w, q3);
        }
        h[tid] = (k0 + k1) + (k2 + k3);
        g_qtab[v * H + tid] = (q0 + q1) + (q2 + q3);
    } else {         // v projection
        const int i = tid - H;
        const float4* wv4 = (const float4*)(Wv + i * H);
        const float4* h4 = (const float4*)hs;
        float a0 = 0.f, a1 = 0.f, a2 = 0.f, a3 = 0.f;
        #pragma unroll
        for (int j = 0; j < 16; j++) {
            float4 ww = wv4[j], hh = h4[j];
            a0 = fmaf(ww.x, hh.x, a0); a1 = fmaf(ww.y, hh.y, a1);
            a2 = fmaf(ww.z, hh.z, a2); a3 = fmaf(ww.w, hh.w, a3);
        }
        g_vtab[v * H + i] = (a0 + a1) + (a2 + a3);
    }
    __syncthreads();

    if (tid < 32) {   // k normalization
        float n = bfly_sum(h[tid] * h[tid] + h[tid + 32] * h[tid + 32]);
        if (tid == 0) s_kinv = 1.0f / fmaxf(sqrtf(n), 1e-12f);
    }
    __syncthreads();
    if (tid < H) {
        float kv = h[tid] * s_kinv;
        g_ktab[v * H + tid] = kv;
        hs[tid] = kv;                 // keep own k row in smem for KK phase
    }

    // Wcomb row v + bcomb[v]
    if (tid < H) {
        float ww = 0.f, w1_ = 0.f;
        #pragma unroll
        for (int l = 0; l < H; l += 2) {
            ww  = fmaf(Wout[v * H + l],     Wrp[l * H + tid],       ww);
            w1_ = fmaf(Wout[v * H + l + 1], Wrp[(l + 1) * H + tid], w1_);
        }
        g_Wcomb[v * H + tid] = ww + w1_;
    }
    if (tid == 0) {
        float bb = bout[v], bb1 = 0.f;
        #pragma unroll
        for (int l = 0; l < H; l += 2) {
            bb  = fmaf(Wout[v * H + l],     brp[l],     bb);
            bb1 = fmaf(Wout[v * H + l + 1], brp[l + 1], bb1);
        }
        g_bcomb[v] = bb + bb1;
    }

    // ---- barrier 1: all tables visible ----
    __syncthreads();
    if (tid == 0) {
        __threadfence();
        atomicAdd(&g_bar1, 1u);
        while (atomicAdd(&g_bar1, 0u) < (unsigned)NBLK) { }
        __threadfence();
    }
    __syncthreads();

    // ================= Phase B: negated KK row v =================
    if (tid < H) {
        const int j = tid;
        const float4* kj4 = (const float4*)(g_ktab + j * H);
        const float4* ki4 = (const float4*)hs;
        float a0 = 0.f, a1 = 0.f, a2 = 0.f, a3 = 0.f;
        #pragma unroll
        for (int l = 0; l < 16; l++) {
            float4 ka = ki4[l], kb = __ldg(kj4 + l);
            a0 = fmaf(ka.x, kb.x, a0); a1 = fmaf(ka.y, kb.y, a1);
            a2 = fmaf(ka.z, kb.z, a2); a3 = fmaf(ka.w, kb.w, a3);
        }
        g_KKn[v * H + j] = -((a0 + a1) + (a2 + a3));
    }
    __syncthreads();
    if (tid == 0) { __threadfence(); atomicAdd(&g_bar2, 1u); }

    // ---- stage vtab into sTab[4096:] (only needs barrier-1 data) ----
    {
        const float4* vg = (const float4*)g_vtab;
        float4* vs = (float4*)(sTab + VOCAB * H);
        #pragma unroll
        for (int i = tid; i < VOCAB * H / 4; i += 128) vs[i] = __ldg(vg + i);
    }

    // ---- R-init: warp w computes batch b, hands off via smem ----
    {
        const unsigned char* myseq = sseq[w];
        const int qid = myseq[LL - 1];
        const float4* q4 = (const float4*)(g_qtab + qid * H);
        const float4* ka = (const float4*)(g_ktab + lo2 * H);
        const float4* kb = (const float4*)(g_ktab + (lo2 + 1) * H);
        float x0 = 0.f, x1 = 0.f, y0 = 0.f, y1 = 0.f;
        #pragma unroll
        for (int i = 0; i < 16; i += 2) {
            float4 q0 = __ldg(q4 + i),     a0 = __ldg(ka + i),     b0 = __ldg(kb + i);
            float4 q1 = __ldg(q4 + i + 1), a1 = __ldg(ka + i + 1), b1 = __ldg(kb + i + 1);
            x0 = fmaf(a0.x, q0.x, x0); x0 = fmaf(a0.y, q0.y, x0);
            x0 = fmaf(a0.z, q0.z, x0); x0 = fmaf(a0.w, q0.w, x0);
            x1 = fmaf(a1.x, q1.x, x1); x1 = fmaf(a1.y, q1.y, x1);
            x1 = fmaf(a1.z, q1.z, x1); x1 = fmaf(a1.w, q1.w, x1);
            y0 = fmaf(b0.x, q0.x, y0); y0 = fmaf(b0.y, q0.y, y0);
            y0 = fmaf(b0.z, q0.z, y0); y0 = fmaf(b0.w, q0.w, y0);
            y1 = fmaf(b1.x, q1.x, y1); y1 = fmaf(b1.y, q1.y, y1);
            y1 = fmaf(b1.z, q1.z, y1); y1 = fmaf(b1.w, q1.w, y1);
        }
        sRi[w][lo2]     = x0 + x1;
        sRi[w][lo2 + 1] = y0 + y1;
    }

    // ---- barrier 2 wait: all KK rows visible ----
    if (tid == 0) {
        while (atomicAdd(&g_bar2, 0u) < (unsigned)NBLK) { }
        __threadfence();
    }
    __syncthreads();

    // ---- stage negated KK into sTab[0:4096) ----
    {
        const float4* gg = (const float4*)g_KKn;
        float4* ks = (float4*)sTab;
        #pragma unroll
        for (int i = tid; i < VOCAB * H / 4; i += 128) ks[i] = __ldg(gg + i);
    }
    __syncthreads();

    // ====== Phase C: one warp per batch, C=4, packed FFMA2, pipelined ======
    {
        const unsigned char* myseq = sseq[w];
        float R0 = sRi[w][lo2], R1 = sRi[w][lo2 + 1];
        unsigned long long Rp = pack2(R0, R1);
        unsigned long long Mp = pack2(0.f, 0.f);

        // 3 single steps: t = 2046, 2045, 2044
        #pragma unroll
        for (int t = LL - 2; t >= LL - 4; --t) {
            const int id = (int)myseq[t];
            const float tt = (id & 1) ? R1 : R0;
            const float s = __shfl_sync(FULL, tt, id >> 1);
            const int ro = (id << 6) + lo2;
            const unsigned long long kp = *(const unsigned long long*)&sTab[ro];
            const unsigned long long vp = *(const unsigned long long*)&sTab[ro + VOCAB * H];
            const unsigned long long sp = pack2(s, s);
            fma2(Rp, kp, sp);
            fma2(Mp, vp, sp);
            unpack2(Rp, R0, R1);
        }

        // 511 groups of 4 with id prefetch; loads fill SHFL shadow
        unsigned ids = *(const unsigned*)(myseq + (LL - 8));
        #pragma unroll 1
        for (int base = LL - 8; base >= 0; base -= 4) {
            const int id0 = (int)(ids >> 24);           // t = base+3 (largest)
            const int id1 = (int)((ids >> 16) & 0xffu);
            const int id2 = (int)((ids >> 8) & 0xffu);
            const int id3 = (int)(ids & 0xffu);
            const int r0 = id0 << 6, r1 = id1 << 6, r2 = id2 << 6, r3 = id3 << 6;

            // gathers d_j = R[id_j]  (depend on previous group's R)
            const float t0 = (id0 & 1) ? R1 : R0;
            const float t1 = (id1 & 1) ? R1 : R0;
            const float t2 = (id2 & 1) ? R1 : R0;
            const float t3 = (id3 & 1) ? R1 : R0;
            const float d0 = __shfl_sync(FULL, t0, id0 >> 1);
            const float d1 = __shfl_sync(FULL, t1, id1 >> 1);
            const float d2 = __shfl_sync(FULL, t2, id2 >> 1);
            const float d3 = __shfl_sync(FULL, t3, id3 >> 1);

            // loads fill the SHFL shadow (independent of R)
            const float g10 = sTab[r1 + id0];
            const float g20 = sTab[r2 + id0], g21 = sTab[r2 + id1];
            const float g30 = sTab[r3 + id0], g31 = sTab[r3 + id1], g32 = sTab[r3 + id2];
            const unsigned long long k0 = *(const unsigned long long*)&sTab[r0 + lo2];
            const unsigned long long k1 = *(const unsigned long long*)&sTab[r1 + lo2];
            const unsigned long long k2 = *(const unsigned long long*)&sTab[r2 + lo2];
            const unsigned long long k3 = *(const unsigned long long*)&sTab[r3 + lo2];
            const unsigned long long v0 = *(const unsigned long long*)&sTab[r0 + lo2 + VOCAB * H];
            const unsigned long long v1 = *(const unsigned long long*)&sTab[r1 + lo2 + VOCAB * H];
            const unsigned long long v2 = *(const unsigned long long*)&sTab[r2 + lo2 + VOCAB * H];
            const unsigned long long v3 = *(const unsigned long long*)&sTab[r3 + lo2 + VOCAB * H];
            ids = *(const unsigned*)(myseq + (base >= 4 ? base - 4 : 0));

            // forward substitution (negated Gram -> pure FMA)
            const float s0 = d0;
            const float s1 = fmaf(g10, s0, d1);
            const float s2 = fmaf(g21, s1, fmaf(g20, s0, d2));
            const float s3 = fmaf(g32, s2, fmaf(g31, s1, fmaf(g30, s0, d3)));
            const unsigned long long sp0 = pack2(s0, s0);
            const unsigned long long sp1 = pack2(s1, s1);
            const unsigned long long sp2 = pack2(s2, s2);
            const unsigned long long sp3 = pack2(s3, s3);

            // R += (-KK row_j) * s_j  (packed, chained)
            fma2(Rp, k0, sp0);
            fma2(Rp, k1, sp1);
            fma2(Rp, k2, sp2);
            fma2(Rp, k3, sp3);
            unpack2(Rp, R0, R1);

            // Mq += vtab row_j * s_j (packed, off critical path)
            fma2(Mp, v0, sp0);
            fma2(Mp, v1, sp1);
            fma2(Mp, v2, sp2);
            fma2(Mp, v3, sp3);
        }

        float M0, M1;
        unpack2(Mp, M0, M1);
        sMq[w][lo2]     = M0;
        sMq[w][lo2 + 1] = M1;
    }
    __syncwarp();

    // ---- epilogue: out = Wcomb @ Mq + bcomb ----
    #pragma unroll
    for (int rr = 0; rr < 2; rr++) {
        const int i = lane + 32 * rr;
        const float4* w4 = (const float4*)(g_Wcomb + i * H);
        const float4* m4 = (const float4*)sMq[w];
        float a0 = 0.f, a1 = 0.f, a2 = 0.f, a3 = 0.f;
        #pragma unroll
        for (int j = 0; j < 16; j++) {
            float4 ww = __ldg(w4 + j);
            float4 m = m4[j];
            a0 = fmaf(ww.x, m.x, a0); a1 = fmaf(ww.y, m.y, a1);
            a2 = fmaf(ww.z, m.z, a2); a3 = fmaf(ww.w, m.w, a3);
        }
        out[b * H + i] = (a0 + a1) + (a2 + a3) + g_bcomb[i];
    }

    // ---- reset spin barriers for the next (graph-replayed) launch ----
    __syncthreads();
    if (tid == 0) {
        __threadfence();
        if (atomicAdd(&g_rst, 1u) == (unsigned)(NBLK - 1)) {
            atomicExch(&g_bar1, 0u);
            atomicExch(&g_bar2, 0u);
            atomicExch(&g_rst, 0u);
        }
    }
}

// ======================================================================
extern "C" void kernel_launch(void* const* d_in, const int* in_sizes, int n_in,
                              void* d_out, int out_size)
{
    (void)in_sizes; (void)n_in; (void)out_size;
    const int*   seq   = (const int*)  d_in[0];
    const float* embed = (const float*)d_in[1];
    const float* W1    = (const float*)d_in[2];
    const float* b1    = (const float*)d_in[3];
    const float* W2    = (const float*)d_in[4];
    const float* b2    = (const float*)d_in[5];
    const float* gamma = (const float*)d_in[6];
    const float* beta  = (const float*)d_in[7];
    const float* Wk    = (const float*)d_in[8];
    const float* Wv    = (const float*)d_in[9];
    const float* Wq    = (const float*)d_in[10];
    const float* Wrp   = (const float*)d_in[11];
    const float* brp   = (const float*)d_in[12];
    const float* Wout  = (const float*)d_in[13];
    const float* bout  = (const float*)d_in[14];

    fused_kernel<<<NBLK, 128>>>(seq, embed, W1, b1, W2, b2, gamma, beta,
                                Wk, Wv, Wq, Wrp, brp, Wout, bout,
                                (float*)d_out);
}

// round 12
// speedup vs baseline: 1.5243x; 1.0997x over previous
#include <cuda_runtime.h>

#define H  64
#define LL 2048
#define VOCAB 64
#define NBLK 64
#define FULL 0xffffffffu

// -------- device-global scratch (no runtime allocation allowed) --------
__device__ __align__(16) float g_ktab[VOCAB * H];    // normalized k per vocab id
__device__ __align__(16) float g_vtab[VOCAB * H];    // v per vocab id
__device__ __align__(16) float g_qtab[VOCAB * H];    // q per vocab id
__device__ __align__(16) float g_KKn[VOCAB * VOCAB]; // NEGATED Gram of k table
__device__ __align__(16) float g_Wcomb[H * H];       // Wout @ Wrp
__device__ __align__(16) float g_bcomb[H];           // Wout @ brp + bout
__device__ unsigned g_bar1 = 0, g_bar2 = 0, g_rst = 0;   // spin barriers

__device__ __forceinline__ float bfly_sum(float v) {
    #pragma unroll
    for (int o = 16; o; o >>= 1) v += __shfl_xor_sync(FULL, v, o);
    return v;
}

// ---- packed f32x2 helpers (sm_103a FFMA2) ----
__device__ __forceinline__ unsigned long long pack2(float lo, float hi) {
    unsigned long long r;
    asm("mov.b64 %0, {%1, %2};" : "=l"(r)
        : "r"(__float_as_uint(lo)), "r"(__float_as_uint(hi)));
    return r;
}
__device__ __forceinline__ void unpack2(unsigned long long p, float& lo, float& hi) {
    unsigned ulo, uhi;
    asm("mov.b64 {%0, %1}, %2;" : "=r"(ulo), "=r"(uhi) : "l"(p));
    lo = __uint_as_float(ulo); hi = __uint_as_float(uhi);
}
__device__ __forceinline__ void fma2(unsigned long long& d,
                                     unsigned long long a, unsigned long long b) {
    asm("fma.rn.f32x2 %0, %1, %2, %0;" : "+l"(d) : "l"(a), "l"(b));
}

// ======================================================================
// Single fused kernel. grid 64, block 128 (1 warp/SMSP).
// Phase C: SHFL-free scan — live R vector in shared memory, gathers are
// pipelined broadcast LDS, commit via ST.64 + __syncwarp (mem-ordered).
// ======================================================================
__global__ void __launch_bounds__(128) fused_kernel(
    const int*   __restrict__ seq,
    const float* __restrict__ embed, const float* __restrict__ W1,
    const float* __restrict__ b1, const float* __restrict__ W2,
    const float* __restrict__ b2, const float* __restrict__ gamma,
    const float* __restrict__ beta, const float* __restrict__ Wk,
    const float* __restrict__ Wv, const float* __restrict__ Wq,
    const float* __restrict__ Wrp, const float* __restrict__ brp,
    const float* __restrict__ Wout, const float* __restrict__ bout,
    float* __restrict__ out)
{
    __shared__ __align__(16) float sTab[2 * VOCAB * H];   // [0:4096) -KK, [4096:8192) vtab
    __shared__ __align__(16) unsigned char sseq[4][LL];   // 8 KB
    __shared__ __align__(16) float e[H], f1[2 * H], h[H], hs[H];
    __shared__ __align__(16) float sRi[4][H];              // live R per warp
    __shared__ __align__(16) float sMq[4][H];              // Mq handoff
    __shared__ float s_mu, s_rstd, s_kinv;

    const int v    = blockIdx.x;
    const int tid  = threadIdx.x;
    const int lane = tid & 31;
    const int w    = tid >> 5;
    const int lo2  = 2 * lane;
    const int b    = v * 4 + w;

    // ---- stage this block's 4 sequences (warp w stages batch b) ----
    {
        const int4* sg = (const int4*)(seq + b * LL);
        uchar4* ssh = (uchar4*)sseq[w];
        #pragma unroll 4
        for (int i = lane; i < LL / 4; i += 32) {
            int4 t = sg[i];
            ssh[i] = make_uchar4((unsigned char)t.x, (unsigned char)t.y,
                                 (unsigned char)t.z, (unsigned char)t.w);
        }
    }

    // ================= Phase A: encode vocab v =================
    if (tid < H) e[tid] = embed[v * H + tid];
    __syncthreads();

    {   // ff1 = relu(W1 e + b1)
        const float4* w4 = (const float4*)(W1 + tid * H);
        const float4* e4 = (const float4*)e;
        float a0 = 0.f, a1 = 0.f, a2 = 0.f, a3 = 0.f;
        #pragma unroll
        for (int i = 0; i < 16; i++) {
            float4 ww = w4[i], ee = e4[i];
            a0 = fmaf(ww.x, ee.x, a0); a1 = fmaf(ww.y, ee.y, a1);
            a2 = fmaf(ww.z, ee.z, a2); a3 = fmaf(ww.w, ee.w, a3);
        }
        f1[tid] = fmaxf((a0 + a1) + (a2 + a3) + b1[tid], 0.0f);
    }
    __syncthreads();

    if (tid < H) {   // h = e + W2 ff1 + b2
        const float4* w4 = (const float4*)(W2 + tid * 2 * H);
        const float4* f4 = (const float4*)f1;
        float a0 = 0.f, a1 = 0.f, a2 = 0.f, a3 = 0.f;
        float b0 = 0.f, c1 = 0.f, c2 = 0.f, b3 = 0.f;
        #pragma unroll
        for (int i = 0; i < 32; i += 2) {
            float4 ww = w4[i], ff = f4[i];
            a0 = fmaf(ww.x, ff.x, a0); a1 = fmaf(ww.y, ff.y, a1);
            a2 = fmaf(ww.z, ff.z, a2); a3 = fmaf(ww.w, ff.w, a3);
            float4 w2_ = w4[i + 1], ff2 = f4[i + 1];
            b0 = fmaf(w2_.x, ff2.x, b0); c1 = fmaf(w2_.y, ff2.y, c1);
            c2 = fmaf(w2_.z, ff2.z, c2); b3 = fmaf(w2_.w, ff2.w, b3);
        }
        h[tid] = e[tid] + ((a0 + a1) + (a2 + a3)) + ((b0 + c1) + (c2 + b3)) + b2[tid];
    }
    __syncthreads();

    if (tid < 32) {   // LayerNorm stats (biased var, eps 1e-5)
        float x = bfly_sum(h[tid] + h[tid + 32]);
        float mu = x * (1.0f / H);
        float c0 = h[tid] - mu, c1_ = h[tid + 32] - mu;
        float vv = bfly_sum(c0 * c0 + c1_ * c1_);
        if (tid == 0) { s_mu = mu; s_rstd = rsqrtf(vv * (1.0f / H) + 1e-5f); }
    }
    __syncthreads();
    if (tid < H) hs[tid] = (h[tid] - s_mu) * s_rstd * gamma[tid] + beta[tid];
    __syncthreads();

    if (tid < H) {   // k (raw) and q projections
        const float4* wk4 = (const float4*)(Wk + tid * H);
        const float4* wq4 = (const float4*)(Wq + tid * H);
        const float4* h4 = (const float4*)hs;
        float k0 = 0.f, k1 = 0.f, k2 = 0.f, k3 = 0.f;
        float q0 = 0.f, q1 = 0.f, q2 = 0.f, q3 = 0.f;
        #pragma unroll
        for (int i = 0; i < 16; i++) {
            float4 wk = wk4[i], wq = wq4[i], hh = h4[i];
            k0 = fmaf(wk.x, hh.x, k0); k1 = fmaf(wk.y, hh.y, k1);
            k2 = fmaf(wk.z, hh.z, k2); k3 = fmaf(wk.w, hh.w, k3);
            q0 = fmaf(wq.x, hh.x, q0); q1 = fmaf(wq.y, hh.y, q1);
            q2 = fmaf(wq.z, hh.z, q2); q3 = fmaf(wq.w, hh.w, q3);
        }
        h[tid] = (k0 + k1) + (k2 + k3);
        g_qtab[v * H + tid] = (q0 + q1) + (q2 + q3);
    } else {         // v projection
        const int i = tid - H;
        const float4* wv4 = (const float4*)(Wv + i * H);
        const float4* h4 = (const float4*)hs;
        float a0 = 0.f, a1 = 0.f, a2 = 0.f, a3 = 0.f;
        #pragma unroll
        for (int j = 0; j < 16; j++) {
            float4 ww = wv4[j], hh = h4[j];
            a0 = fmaf(ww.x, hh.x, a0); a1 = fmaf(ww.y, hh.y, a1);
            a2 = fmaf(ww.z, hh.z, a2); a3 = fmaf(ww.w, hh.w, a3);
        }
        g_vtab[v * H + i] = (a0 + a1) + (a2 + a3);
    }
    __syncthreads();

    if (tid < 32) {   // k normalization
        float n = bfly_sum(h[tid] * h[tid] + h[tid + 32] * h[tid + 32]);
        if (tid == 0) s_kinv = 1.0f / fmaxf(sqrtf(n), 1e-12f);
    }
    __syncthreads();
    if (tid < H) {
        float kv = h[tid] * s_kinv;
        g_ktab[v * H + tid] = kv;
        hs[tid] = kv;                 // keep own k row in smem for KK phase
    }

    // Wcomb row v + bcomb[v]
    if (tid < H) {
        float ww = 0.f, w1_ = 0.f;
        #pragma unroll
        for (int l = 0; l < H; l += 2) {
            ww  = fmaf(Wout[v * H + l],     Wrp[l * H + tid],       ww);
            w1_ = fmaf(Wout[v * H + l + 1], Wrp[(l + 1) * H + tid], w1_);
        }
        g_Wcomb[v * H + tid] = ww + w1_;
    }
    if (tid == 0) {
        float bb = bout[v], bb1 = 0.f;
        #pragma unroll
        for (int l = 0; l < H; l += 2) {
            bb  = fmaf(Wout[v * H + l],     brp[l],     bb);
            bb1 = fmaf(Wout[v * H + l + 1], brp[l + 1], bb1);
        }
        g_bcomb[v] = bb + bb1;
    }

    // ---- barrier 1: all tables visible ----
    __syncthreads();
    if (tid == 0) {
        __threadfence();
        atomicAdd(&g_bar1, 1u);
        while (atomicAdd(&g_bar1, 0u) < (unsigned)NBLK) { }
        __threadfence();
    }
    __syncthreads();

    // ================= Phase B: negated KK row v =================
    if (tid < H) {
        const int j = tid;
        const float4* kj4 = (const float4*)(g_ktab + j * H);
        const float4* ki4 = (const float4*)hs;
        float a0 = 0.f, a1 = 0.f, a2 = 0.f, a3 = 0.f;
        #pragma unroll
        for (int l = 0; l < 16; l++) {
            float4 ka = ki4[l], kb = __ldg(kj4 + l);
            a0 = fmaf(ka.x, kb.x, a0); a1 = fmaf(ka.y, kb.y, a1);
            a2 = fmaf(ka.z, kb.z, a2); a3 = fmaf(ka.w, kb.w, a3);
        }
        g_KKn[v * H + j] = -((a0 + a1) + (a2 + a3));
    }
    __syncthreads();
    if (tid == 0) { __threadfence(); atomicAdd(&g_bar2, 1u); }

    // ---- stage vtab into sTab[4096:] (only needs barrier-1 data) ----
    {
        const float4* vg = (const float4*)g_vtab;
        float4* vs = (float4*)(sTab + VOCAB * H);
        #pragma unroll
        for (int i = tid; i < VOCAB * H / 4; i += 128) vs[i] = __ldg(vg + i);
    }

    // ---- R-init: warp w computes batch b, R lives in sRi[w] ----
    {
        const unsigned char* myseq = sseq[w];
        const int qid = myseq[LL - 1];
        const float4* q4 = (const float4*)(g_qtab + qid * H);
        const float4* ka = (const float4*)(g_ktab + lo2 * H);
        const float4* kb = (const float4*)(g_ktab + (lo2 + 1) * H);
        float x0 = 0.f, x1 = 0.f, y0 = 0.f, y1 = 0.f;
        #pragma unroll
        for (int i = 0; i < 16; i += 2) {
            float4 q0 = __ldg(q4 + i),     a0 = __ldg(ka + i),     b0 = __ldg(kb + i);
            float4 q1 = __ldg(q4 + i + 1), a1 = __ldg(ka + i + 1), b1 = __ldg(kb + i + 1);
            x0 = fmaf(a0.x, q0.x, x0); x0 = fmaf(a0.y, q0.y, x0);
            x0 = fmaf(a0.z, q0.z, x0); x0 = fmaf(a0.w, q0.w, x0);
            x1 = fmaf(a1.x, q1.x, x1); x1 = fmaf(a1.y, q1.y, x1);
            x1 = fmaf(a1.z, q1.z, x1); x1 = fmaf(a1.w, q1.w, x1);
            y0 = fmaf(b0.x, q0.x, y0); y0 = fmaf(b0.y, q0.y, y0);
            y0 = fmaf(b0.z, q0.z, y0); y0 = fmaf(b0.w, q0.w, y0);
            y1 = fmaf(b1.x, q1.x, y1); y1 = fmaf(b1.y, q1.y, y1);
            y1 = fmaf(b1.z, q1.z, y1); y1 = fmaf(b1.w, q1.w, y1);
        }
        sRi[w][lo2]     = x0 + x1;
        sRi[w][lo2 + 1] = y0 + y1;
    }

    // ---- barrier 2 wait: all KK rows visible ----
    if (tid == 0) {
        while (atomicAdd(&g_bar2, 0u) < (unsigned)NBLK) { }
        __threadfence();
    }
    __syncthreads();

    // ---- stage negated KK into sTab[0:4096) ----
    {
        const float4* gg = (const float4*)g_KKn;
        float4* ks = (float4*)sTab;
        #pragma unroll
        for (int i = tid; i < VOCAB * H / 4; i += 128) ks[i] = __ldg(gg + i);
    }
    __syncthreads();

    // ====== Phase C: SHFL-free scan — R in smem, gathers via LDS ======
    {
        const unsigned char* myseq = sseq[w];
        float* sRw = sRi[w];                        // live R for this warp
        unsigned long long Rp = pack2(sRw[lo2], sRw[lo2 + 1]);
        unsigned long long Mp = pack2(0.f, 0.f);

        // 3 single steps: t = 2046, 2045, 2044
        #pragma unroll
        for (int t = LL - 2; t >= LL - 4; --t) {
            const int id = (int)myseq[t];
            const float s = sRw[id];                // broadcast LDS
            const int ro = (id << 6) + lo2;
            const unsigned long long kp = *(const unsigned long long*)&sTab[ro];
            const unsigned long long vp = *(const unsigned long long*)&sTab[ro + VOCAB * H];
            const unsigned long long sp = pack2(s, s);
            fma2(Rp, kp, sp);
            fma2(Mp, vp, sp);
            *(unsigned long long*)&sRw[lo2] = Rp;   // commit R
            __syncwarp();
        }

        // 511 groups of 4 with id prefetch
        unsigned ids = *(const unsigned*)(myseq + (LL - 8));
        #pragma unroll 1
        for (int base = LL - 8; base >= 0; base -= 4) {
            const int id0 = (int)(ids >> 24);           // t = base+3 (largest)
            const int id1 = (int)((ids >> 16) & 0xffu);
            const int id2 = (int)((ids >> 8) & 0xffu);
            const int id3 = (int)(ids & 0xffu);
            const int r0 = id0 << 6, r1 = id1 << 6, r2 = id2 << 6, r3 = id3 << 6;

            // gathers d_j = R[id_j] — pipelined broadcast LDS (no SHFL)
            const float d0 = sRw[id0];
            const float d1 = sRw[id1];
            const float d2 = sRw[id2];
            const float d3 = sRw[id3];

            // loads fill the LDS shadow (independent of R)
            const float g10 = sTab[r1 + id0];
            const float g20 = sTab[r2 + id0], g21 = sTab[r2 + id1];
            const float g30 = sTab[r3 + id0], g31 = sTab[r3 + id1], g32 = sTab[r3 + id2];
            const unsigned long long k0 = *(const unsigned long long*)&sTab[r0 + lo2];
            const unsigned long long k1 = *(const unsigned long long*)&sTab[r1 + lo2];
            const unsigned long long k2 = *(const unsigned long long*)&sTab[r2 + lo2];
            const unsigned long long k3 = *(const unsigned long long*)&sTab[r3 + lo2];
            const unsigned long long v0 = *(const unsigned long long*)&sTab[r0 + lo2 + VOCAB * H];
            const unsigned long long v1 = *(const unsigned long long*)&sTab[r1 + lo2 + VOCAB * H];
            const unsigned long long v2 = *(const unsigned long long*)&sTab[r2 + lo2 + VOCAB * H];
            const unsigned long long v3 = *(const unsigned long long*)&sTab[r3 + lo2 + VOCAB * H];
            ids = *(const unsigned*)(myseq + (base >= 4 ? base - 4 : 0));

            // forward substitution (negated Gram -> pure FMA)
            const float s0 = d0;
            const float s1 = fmaf(g10, s0, d1);
            const float s2 = fmaf(g21, s1, fmaf(g20, s0, d2));
            const float s3 = fmaf(g32, s2, fmaf(g31, s1, fmaf(g30, s0, d3)));
            const unsigned long long sp0 = pack2(s0, s0);
            const unsigned long long sp1 = pack2(s1, s1);
            const unsigned long long sp2 = pack2(s2, s2);
            const unsigned long long sp3 = pack2(s3, s3);

            // R += (-KK row_j) * s_j  (packed, chained) -> commit to smem
            fma2(Rp, k0, sp0);
            fma2(Rp, k1, sp1);
            fma2(Rp, k2, sp2);
            fma2(Rp, k3, sp3);
            *(unsigned long long*)&sRw[lo2] = Rp;
            __syncwarp();

            // Mq += vtab row_j * s_j (packed; fills the next gather's shadow)
            fma2(Mp, v0, sp0);
            fma2(Mp, v1, sp1);
            fma2(Mp, v2, sp2);
            fma2(Mp, v3, sp3);
        }

        float M0, M1;
        unpack2(Mp, M0, M1);
        sMq[w][lo2]     = M0;
        sMq[w][lo2 + 1] = M1;
    }
    __syncwarp();

    // ---- epilogue: out = Wcomb @ Mq + bcomb ----
    #pragma unroll
    for (int rr = 0; rr < 2; rr++) {
        const int i = lane + 32 * rr;
        const float4* w4 = (const float4*)(g_Wcomb + i * H);
        const float4* m4 = (const float4*)sMq[w];
        float a0 = 0.f, a1 = 0.f, a2 = 0.f, a3 = 0.f;
        #pragma unroll
        for (int j = 0; j < 16; j++) {
            float4 ww = __ldg(w4 + j);
            float4 m = m4[j];
            a0 = fmaf(ww.x, m.x, a0); a1 = fmaf(ww.y, m.y, a1);
            a2 = fmaf(ww.z, m.z, a2); a3 = fmaf(ww.w, m.w, a3);
        }
        out[b * H + i] = (a0 + a1) + (a2 + a3) + g_bcomb[i];
    }

    // ---- reset spin barriers for the next (graph-replayed) launch ----
    __syncthreads();
    if (tid == 0) {
        __threadfence();
        if (atomicAdd(&g_rst, 1u) == (unsigned)(NBLK - 1)) {
            atomicExch(&g_bar1, 0u);
            atomicExch(&g_bar2, 0u);
            atomicExch(&g_rst, 0u);
        }
    }
}

// ======================================================================
extern "C" void kernel_launch(void* const* d_in, const int* in_sizes, int n_in,
                              void* d_out, int out_size)
{
    (void)in_sizes; (void)n_in; (void)out_size;
    const int*   seq   = (const int*)  d_in[0];
    const float* embed = (const float*)d_in[1];
    const float* W1    = (const float*)d_in[2];
    const float* b1    = (const float*)d_in[3];
    const float* W2    = (const float*)d_in[4];
    const float* b2    = (const float*)d_in[5];
    const float* gamma = (const float*)d_in[6];
    const float* beta  = (const float*)d_in[7];
    const float* Wk    = (const float*)d_in[8];
    const float* Wv    = (const float*)d_in[9];
    const float* Wq    = (const float*)d_in[10];
    const float* Wrp   = (const float*)d_in[11];
    const float* brp   = (const float*)d_in[12];
    const float* Wout  = (const float*)d_in[13];
    const float* bout  = (const float*)d_in[14];

    fused_kernel<<<NBLK, 128>>>(seq, embed, W1, b1, W2, b2, gamma, beta,
                                Wk, Wv, Wq, Wrp, brp, Wout, bout,
                                (float*)d_out);
}